// round 8
// baseline (speedup 1.0000x reference)
#include <cuda_runtime.h>
#include <cstdint>

#define N_NODES 100000
#define N_EDGES 3200000
#define N_FEAT  24
#define FPAD    32                 // padded feature stride (128 bytes)
#define LAYERS  6
#define EDGE_CAP 4000000           // sum ceil(len/8)*8 <= E + 7N = 3.9M
#define BUILD_BLOCKS  148
#define BUILD_THREADS 1024
#define CHUNK 676                  // ceil(N_NODES / BUILD_BLOCKS)

// ---------------------------------------------------------------------------
// Scratch (allocation-free rule: __device__ globals).
// Padded CSR: each row's segment in g_edge is padded to a multiple of 8.
// Pad slots are NEVER written by any kernel; __device__ globals are
// zero-initialized, so pads are permanently (val=0, off=0) -> gather reads
// src[0..] scaled by 0. Deterministic layout -> replay-safe.
// Feature buffers are padded to FPAD=32 floats/row (128B): every gather
// lands in a single L1 line. Pad columns likewise stay zero forever.
// ---------------------------------------------------------------------------
__device__ __align__(16) float  g_bufP[(size_t)N_NODES * FPAD];
__device__ __align__(16) float  g_bufQ[(size_t)N_NODES * FPAD];
__device__ __align__(16) float2 g_edge[EDGE_CAP];   // (val, col*128 bits)
__device__ int g_cnt[N_NODES];        // real row lengths
__device__ int g_rowptr[N_NODES + 1]; // padded exclusive prefix
__device__ int g_cursor[N_NODES];
__device__ int g_bsum[BUILD_BLOCKS];
__device__ int g_boff[BUILD_BLOCKS];
// Monotone: int32 inputs -> set to 1 every run (idempotent); int64 -> stays 0.
__device__ int g_flag = 0;
// Monotone ticket barrier counter; never reset -> replay-safe.
__device__ unsigned g_bar = 0;

// ---------------------------------------------------------------------------
// Software grid barrier (persistent build kernel; 148 blocks = wave 1).
// ---------------------------------------------------------------------------
__device__ __forceinline__ void grid_barrier() {
    __syncthreads();
    if (threadIdx.x == 0) {
        __threadfence();
        unsigned ticket = atomicAdd(&g_bar, 1u);
        unsigned target = (ticket / BUILD_BLOCKS + 1u) * BUILD_BLOCKS;
        unsigned v;
        do {
            asm volatile("ld.global.acquire.gpu.u32 %0, [%1];"
                         : "=r"(v) : "l"(&g_bar));
            if (v < target) __nanosleep(64);
        } while (v < target);
    }
    __syncthreads();
}

__device__ __forceinline__ int load_idx(const void* p, int e, int flag) {
    int v = (flag == 1) ? ((const int*)p)[e] : (int)((const long long*)p)[e];
    return min(max(v, 0), N_NODES - 1);   // fault guard
}

// ---------------------------------------------------------------------------
// Persistent single-launch CSR build + x copy-in:
//   phase 0: zero counts, dtype probe, copy x -> padded g_bufP
//   phase 1: row histogram
//   phase 2: exclusive scan of PADDED counts -> g_rowptr, g_cursor
//   phase 3: scatter (val, col*128) into row-sorted padded g_edge
// ---------------------------------------------------------------------------
__global__ void __launch_bounds__(BUILD_THREADS)
build_csr_kernel(const void* __restrict__ rptr,
                 const void* __restrict__ cptr,
                 const float* __restrict__ vals,
                 const float* __restrict__ x) {
    const int tid    = threadIdx.x;
    const int gid    = blockIdx.x * BUILD_THREADS + tid;
    const int stride = BUILD_BLOCKS * BUILD_THREADS;

    // --- phase 0 ---
    for (int i = gid; i < N_NODES; i += stride) g_cnt[i] = 0;
    const int* p32 = (const int*)rptr;
    for (int i = gid; i < N_EDGES / 2; i += stride)
        if (p32[2 * i + 1] != 0) g_flag = 1;
    // copy x (stride 24) into padded bufP (stride 32); pad cols untouched (=0)
    for (int i = gid; i < N_NODES * N_FEAT; i += stride) {
        int r = i / N_FEAT, f = i - r * N_FEAT;
        g_bufP[r * FPAD + f] = x[i];
    }
    grid_barrier();

    const int flag = g_flag;

    // --- phase 1: histogram ---
    for (int e = gid; e < N_EDGES; e += stride)
        atomicAdd(&g_cnt[load_idx(rptr, e, flag)], 1);
    grid_barrier();

    // --- phase 2a: block-local exclusive scan of padded counts ---
    {
        __shared__ int s_w[32];
        int lane = tid & 31, wid = tid >> 5;
        int i = blockIdx.x * CHUNK + tid;
        int v = (tid < CHUNK && i < N_NODES) ? ((g_cnt[i] + 7) & ~7) : 0;
        int s = v;
        #pragma unroll
        for (int off = 1; off < 32; off <<= 1) {
            int n = __shfl_up_sync(0xffffffffu, s, off);
            if (lane >= off) s += n;
        }
        if (lane == 31) s_w[wid] = s;
        __syncthreads();
        if (wid == 0) {
            int ws = s_w[lane];
            #pragma unroll
            for (int off = 1; off < 32; off <<= 1) {
                int n = __shfl_up_sync(0xffffffffu, ws, off);
                if (lane >= off) ws += n;
            }
            s_w[lane] = ws;
        }
        __syncthreads();
        int woff = (wid > 0) ? s_w[wid - 1] : 0;
        if (tid < CHUNK && i < N_NODES) g_rowptr[i] = woff + s - v;
        if (tid == BUILD_THREADS - 1) g_bsum[blockIdx.x] = s_w[31];
    }
    grid_barrier();

    // --- phase 2b: block 0 scans the 148 block sums ---
    {
        __shared__ int sb[BUILD_BLOCKS];
        if (blockIdx.x == 0) {
            if (tid < BUILD_BLOCKS) sb[tid] = g_bsum[tid];
            __syncthreads();
            for (int off = 1; off < BUILD_BLOCKS; off <<= 1) {
                int t = (tid < BUILD_BLOCKS && tid >= off) ? sb[tid - off] : 0;
                __syncthreads();
                if (tid < BUILD_BLOCKS) sb[tid] += t;
                __syncthreads();
            }
            if (tid < BUILD_BLOCKS) g_boff[tid] = sb[tid] - g_bsum[tid];
            if (tid == BUILD_BLOCKS - 1) g_rowptr[N_NODES] = sb[BUILD_BLOCKS - 1];
        }
    }
    grid_barrier();

    // --- phase 2c: add block offsets; init cursors ---
    for (int i = gid; i < N_NODES; i += stride) {
        int r = g_rowptr[i] + g_boff[i / CHUNK];
        g_rowptr[i] = r;
        g_cursor[i] = r;
    }
    grid_barrier();

    // --- phase 3: place edges (payload: val, col*128 byte offset) ---
    for (int e = gid; e < N_EDGES; e += stride) {
        int r = load_idx(rptr, e, flag);
        int c = load_idx(cptr, e, flag);
        int pos = atomicAdd(&g_cursor[r], 1);
        g_edge[pos] = make_float2(vals[e], __int_as_float(c * (FPAD * 4)));
    }
}

// ---------------------------------------------------------------------------
// CSR SpMM (padded): one warp per row, lane f owns feature f. No masking,
// no remainder: rows are padded to 8-edge multiples with permanent-zero pad
// entries; loop is ceil(len/8) full float4-aligned batches. src stride is
// always FPAD (128B) -> every gather hits a single L1 line. Lanes 24-31
// read zero pad columns and never write. dst stride parameterized: FPAD for
// intermediate layers, N_FEAT for the final write to d_out.
// ---------------------------------------------------------------------------
__global__ void __launch_bounds__(256)
spmm_csr_kernel(const float* __restrict__ src, float* __restrict__ dst,
                int dst_stride) {
    int w    = (blockIdx.x * blockDim.x + threadIdx.x) >> 5;  // row
    int lane = threadIdx.x & 31;

    int start = g_rowptr[w];          // multiple of 8
    int end   = start + g_cnt[w];     // loop rounds up via pads
    const char* sp = (const char*)src + lane * 4;

    float a0 = 0.f, a1 = 0.f, a2 = 0.f, a3 = 0.f;
    float a4 = 0.f, a5 = 0.f, a6 = 0.f, a7 = 0.f;

    for (int e = start; e < end; e += 8) {
        float4 p0 = *(const float4*)&g_edge[e + 0];
        float4 p1 = *(const float4*)&g_edge[e + 2];
        float4 p2 = *(const float4*)&g_edge[e + 4];
        float4 p3 = *(const float4*)&g_edge[e + 6];
        a0 = fmaf(p0.x, *(const float*)(sp + __float_as_int(p0.y)), a0);
        a1 = fmaf(p0.z, *(const float*)(sp + __float_as_int(p0.w)), a1);
        a2 = fmaf(p1.x, *(const float*)(sp + __float_as_int(p1.y)), a2);
        a3 = fmaf(p1.z, *(const float*)(sp + __float_as_int(p1.w)), a3);
        a4 = fmaf(p2.x, *(const float*)(sp + __float_as_int(p2.y)), a4);
        a5 = fmaf(p2.z, *(const float*)(sp + __float_as_int(p2.w)), a5);
        a6 = fmaf(p3.x, *(const float*)(sp + __float_as_int(p3.y)), a6);
        a7 = fmaf(p3.z, *(const float*)(sp + __float_as_int(p3.w)), a7);
    }

    float acc = ((a0 + a1) + (a2 + a3)) + ((a4 + a5) + (a6 + a7));
    if (lane < N_FEAT) dst[w * dst_stride + lane] = acc;
}

// ---------------------------------------------------------------------------
// kernel_launch: one build launch, then 6 SpMMs. x is copied into padded
// bufP inside build; chain P->Q->P->Q->P->Q->out. Default stream, no syncs,
// no allocations -> graph-capturable.
// ---------------------------------------------------------------------------
extern "C" void kernel_launch(void* const* d_in, const int* in_sizes, int n_in,
                              void* d_out, int out_size) {
    const float* x    = (const float*)d_in[0];  // [N_NODES, N_FEAT]
    const float* vals = (const float*)d_in[1];  // [N_EDGES]
    const void*  rraw = d_in[2];                // [N_EDGES] int32 or int64
    const void*  craw = d_in[3];                // [N_EDGES] int32 or int64
    float* out = (float*)d_out;                 // [N_NODES, N_FEAT]

    float* bufP;
    float* bufQ;
    cudaGetSymbolAddress((void**)&bufP, g_bufP);
    cudaGetSymbolAddress((void**)&bufQ, g_bufQ);

    const int sblocks = N_NODES / 8;   // 12500 blocks, warp per row

    build_csr_kernel<<<BUILD_BLOCKS, BUILD_THREADS>>>(rraw, craw, vals, x);

    // 6 layers: P -> Q -> P -> Q -> P -> Q -> out
    const float* srcs[LAYERS] = { bufP, bufQ, bufP, bufQ, bufP, bufQ };
    float*       dsts[LAYERS] = { bufQ, bufP, bufQ, bufP, bufQ, out };
    int          dstr[LAYERS] = { FPAD, FPAD, FPAD, FPAD, FPAD, N_FEAT };

    for (int l = 0; l < LAYERS; l++) {
        spmm_csr_kernel<<<sblocks, 256>>>(srcs[l], dsts[l], dstr[l]);
    }
}